// round 13
// baseline (speedup 1.0000x reference)
#include <cuda_runtime.h>
#include <cstdint>

// SimplePatchScorer: out[b, j] = dot(W, permuted_patch_row(b, j)) + bias
//   x: (512, 3, 224, 224) fp32, W: (1,768), b: (1,) -> out: (512, 196)
//
// flat[u], u = s*588 + v; s = ph*16+pw; v = c*196 + hn*14 + wn.
// out[b,j] = sum_t W[t]*flat[768j+t] + bias.
// lcm(588,768)=37632 => 4 groups/image: s in [64g,64g+64), j in [49g,49g+49).
//
// v11 = v9 skeleton (quarter tiles 16 s' rows, 256 thr, 5 CTAs/SM, 4-way
// stagger, XOR-swizzled smem, f32x2 math) + PER-LANE REGISTER W CACHE:
// for row-aligned segments lane l always needs W[4l+128k], k=0..5 ->
// 6 float4 in registers, loaded once. Full rows (46/49) run a fully
// unrolled 6-step loop with ONE smem load per 4 elems (W-LDS eliminated,
// phase-2 smem traffic halved). Straddle rows (3/49) use the smem-W path.

#define VPAD      604          // mult of 4; phase-2 float4 never straddles rows
#define QUARTER_U 9408         // 16 * 588
#define THREADS   256

__global__ __launch_bounds__(THREADS, 5)
void patch_scorer_v11(const float* __restrict__ x,
                      const float* __restrict__ W,
                      const float* __restrict__ bias,
                      float* __restrict__ out)
{
    extern __shared__ float smem[];
    float* Y  = smem;               // [16][604], XOR-swizzled granules
    float* Ws = smem + 16 * VPAD;   // [768] (straddle-row fallback only)

    const int tid  = threadIdx.x;
    const int g    = blockIdx.x & 3;
    const int b    = blockIdx.x >> 2;
    const int lane = tid & 31;
    const int warp = tid >> 5;      // 8 warps

    const float* xb = x + (size_t)b * 150528;
    const uint32_t ybase = (uint32_t)__cvta_generic_to_shared(Y);
    const uint32_t wbase = (uint32_t)__cvta_generic_to_shared(Ws);

    if (tid < 192)                  // 192 float4 = 768 floats
        ((float4*)Ws)[tid] = ((const float4*)W)[tid];
    // visible after the first phase-1 __syncthreads

    // ---- per-lane register W cache: W[4*lane + 128k .. +3], k = 0..5 ----
    unsigned long long wq01[6], wq23[6];
    #pragma unroll
    for (int k = 0; k < 6; k++) {
        asm("ld.global.nc.v2.b64 {%0,%1}, [%2];"
            : "=l"(wq01[k]), "=l"(wq23[k])
            : "l"(W + 128 * k + 4 * lane));
    }

    float acc[7];
    #pragma unroll
    for (int i = 0; i < 7; i++) acc[i] = 0.f;

    const int q0 = (blockIdx.x >> 2) & 3;   // stagger start quarter

    for (int qq = 0; qq < 4; qq++) {
        const int q = (q0 + qq) & 3;
        if (qq) __syncthreads();    // previous compute done before overwrite

        // ---- Phase 1: stream quarter q's region -> swizzled smem tile ----
        // ph = 4g + q; 42 rows x 56 float4 = 2352 float4 over 256 threads.
        {
            const int hoff = 4 * g + q;
            int w4 = tid % 56;
            int r  = tid / 56;
            int hn = r % 14;
            int c  = r / 14;
            #pragma unroll 2
            for (int e4 = tid; e4 < 2352; e4 += THREADS) {
                int w = w4 << 2;
                float4 val = __ldcs((const float4*)(xb +
                    (size_t)c * 50176 + (hn * 16 + hoff) * 224 + w));

                int pw  = w & 15;               // 0,4,8,12
                int wn  = w >> 4;
                int col = c * 196 + hn * 14 + wn;
                int xcol = ((((col >> 2) ^ (pw >> 2)) << 2)) | (col & 3);
                float* dst = Y + pw * VPAD + xcol;
                dst[0 * VPAD] = val.x;
                dst[1 * VPAD] = val.y;
                dst[2 * VPAD] = val.z;
                dst[3 * VPAD] = val.w;

                w4 += 32;                       // e4 += 256 carry chain
                int rinc = 4;
                if (w4 >= 56) { w4 -= 56; rinc = 5; }
                hn += rinc;
                if (hn >= 14) { hn -= 14; c++; }
            }
        }
        __syncthreads();

        // ---- Phase 2: dot over u' in [9408q, 9408q+9408) ----
        const int rlo = QUARTER_U * q, rhi = rlo + QUARTER_U;
        #pragma unroll
        for (int i = 0; i < 7; i++) {
            int jl = warp + 8 * i;
            if (jl < 49) {
                const int ulo = 768 * jl, uhi = ulo + 768;
                if (ulo >= rhi || uhi <= rlo) continue;   // row not in tile

                if (ulo >= rlo && uhi <= rhi) {
                    // ===== full row: register-W path, fully unrolled =====
                    int u  = ulo + 4 * lane;
                    int sp = (unsigned)u / 588u;
                    int v  = u - sp * 588;
                    int rl = sp - 16 * q;
                    uint32_t ya = ybase + 4u * (rl * VPAD
                                 + ((((v >> 2) ^ (rl >> 2)) << 2)));
                    unsigned long long p01 = 0, p23 = 0;
                    #pragma unroll
                    for (int k = 0; k < 6; k++) {
                        unsigned long long y01, y23;
                        asm volatile("ld.shared.v2.b64 {%0,%1}, [%2];"
                                     : "=l"(y01), "=l"(y23) : "r"(ya));
                        asm volatile("fma.rn.f32x2 %0, %1, %2, %0;"
                                     : "+l"(p01) : "l"(y01), "l"(wq01[k]));
                        asm volatile("fma.rn.f32x2 %0, %1, %2, %0;"
                                     : "+l"(p23) : "l"(y23), "l"(wq23[k]));
                        if (k < 5) {
                            v += 128;
                            if (v >= 588) {
                                v -= 588; rl++;
                                ya = ybase + 4u * (rl * VPAD
                                     + ((((v >> 2) ^ (rl >> 2)) << 2)));
                            } else {
                                ya += 512;
                            }
                        }
                    }
                    acc[i] += (__uint_as_float((uint32_t)p01)
                             + __uint_as_float((uint32_t)(p01 >> 32)))
                            + (__uint_as_float((uint32_t)p23)
                             + __uint_as_float((uint32_t)(p23 >> 32)));
                } else {
                    // ===== straddle row: smem-W fallback =====
                    int clo = max(ulo, rlo);
                    int chi = min(uhi, rhi);
                    int u   = clo + 4 * lane;
                    if (u < chi) {
                        int sp = (unsigned)u / 588u;
                        int v  = u - sp * 588;
                        int rl = sp - 16 * q;
                        uint32_t ya = ybase + 4u * (rl * VPAD
                                     + ((((v >> 2) ^ (rl >> 2)) << 2)));
                        uint32_t wa = wbase + 4u * (u - ulo);
                        unsigned long long p01 = 0, p23 = 0;
                        while (u < chi) {
                            unsigned long long y01, y23, w01, w23;
                            asm volatile("ld.shared.v2.b64 {%0,%1}, [%2];"
                                         : "=l"(y01), "=l"(y23) : "r"(ya));
                            asm volatile("ld.shared.v2.b64 {%0,%1}, [%2];"
                                         : "=l"(w01), "=l"(w23) : "r"(wa));
                            asm volatile("fma.rn.f32x2 %0, %1, %2, %0;"
                                         : "+l"(p01) : "l"(y01), "l"(w01));
                            asm volatile("fma.rn.f32x2 %0, %1, %2, %0;"
                                         : "+l"(p23) : "l"(y23), "l"(w23));
                            u  += 128;
                            wa += 512;
                            v  += 128;
                            if (v >= 588) {
                                v -= 588; rl++;
                                ya = ybase + 4u * (rl * VPAD
                                     + ((((v >> 2) ^ (rl >> 2)) << 2)));
                            } else {
                                ya += 512;
                            }
                        }
                        acc[i] += (__uint_as_float((uint32_t)p01)
                                 + __uint_as_float((uint32_t)(p01 >> 32)))
                                + (__uint_as_float((uint32_t)p23)
                                 + __uint_as_float((uint32_t)(p23 >> 32)));
                    }
                }
            }
        }
    }

    // ---- final warp reductions + store ----
    const float bv = __ldg(bias);
    #pragma unroll
    for (int i = 0; i < 7; i++) {
        int jl = warp + 8 * i;
        if (jl < 49) {
            float a = acc[i];
            #pragma unroll
            for (int off = 16; off; off >>= 1)
                a += __shfl_xor_sync(0xffffffffu, a, off);
            if (lane == 0)
                out[b * 196 + 49 * g + jl] = a + bv;
        }
    }
}

extern "C" void kernel_launch(void* const* d_in, const int* in_sizes, int n_in,
                              void* d_out, int out_size)
{
    const float* x  = (const float*)d_in[0];
    const float* W  = (const float*)d_in[1];
    const float* bb = (const float*)d_in[2];
    float* out = (float*)d_out;

    const int smem_bytes = (16 * VPAD + 768) * sizeof(float);  // ~40.8 KB
    cudaFuncSetAttribute(patch_scorer_v11,
                         cudaFuncAttributeMaxDynamicSharedMemorySize, smem_bytes);

    patch_scorer_v11<<<512 * 4, THREADS, smem_bytes>>>(x, W, bb, out);
}

// round 14
// speedup vs baseline: 1.0862x; 1.0862x over previous
#include <cuda_runtime.h>
#include <cstdint>

// SimplePatchScorer: out[b, j] = dot(W, permuted_patch_row(b, j)) + bias
//   x: (512, 3, 224, 224) fp32, W: (1,768), b: (1,) -> out: (512, 196)
//
// flat[u], u = s*588 + v; s = ph*16+pw; v = c*196 + hn*14 + wn.
// out[b,j] = sum_t W[t]*flat[768j+t] + bias.
// lcm(588,768)=37632 => 4 groups/image: s in [64g,64g+64), j in [49g,49g+49).
//
// v12: U-ORDER smem layout. Phase 1 scatters each loaded float4 to
// Y[u-9408q] (+0,+588,+1176,+1764) -> phase 2 reads Y contiguously:
// full rows are a branch-free 6-step unroll of LDS.v2.b64 + 2x fma.f32x2
// against a per-lane register W cache (W[4*lane+128k], k=0..5) — no div,
// no wrap branch, no swizzle, no smem W. Straddle rows (j=12,24,36) use a
// contiguous smem-W loop. Quarter tiles 37.6KB+W -> 5 CTAs/SM, 4-way stagger.

#define TILE_F  9408           // 16 * 588 floats per quarter tile
#define THREADS 256

__global__ __launch_bounds__(THREADS, 5)
void patch_scorer_v12(const float* __restrict__ x,
                      const float* __restrict__ W,
                      const float* __restrict__ bias,
                      float* __restrict__ out)
{
    extern __shared__ float smem[];
    float* Y  = smem;               // [9408], u-order (local to tile)
    float* Ws = smem + TILE_F;      // [768], straddle-row fallback

    const int tid  = threadIdx.x;
    const int g    = blockIdx.x & 3;
    const int b    = blockIdx.x >> 2;
    const int lane = tid & 31;
    const int warp = tid >> 5;      // 8 warps

    const float* xb = x + (size_t)b * 150528;
    const uint32_t ybase = (uint32_t)__cvta_generic_to_shared(Y);
    const uint32_t wbase = (uint32_t)__cvta_generic_to_shared(Ws);

    if (tid < 192)                  // 192 float4 = 768 floats
        ((float4*)Ws)[tid] = ((const float4*)W)[tid];
    // visible after the first phase-1 __syncthreads

    // ---- per-lane register W cache: W[4*lane + 128k .. +3], k = 0..5 ----
    unsigned long long wq01[6], wq23[6];
    #pragma unroll
    for (int k = 0; k < 6; k++) {
        asm("ld.global.nc.v2.b64 {%0,%1}, [%2];"
            : "=l"(wq01[k]), "=l"(wq23[k])
            : "l"(W + 128 * k + 4 * lane));
    }

    float acc[7];
    #pragma unroll
    for (int i = 0; i < 7; i++) acc[i] = 0.f;

    const int q0 = (blockIdx.x >> 2) & 3;   // 4-way stagger

    for (int qq = 0; qq < 4; qq++) {
        const int q = (q0 + qq) & 3;
        if (qq) __syncthreads();    // previous compute done before overwrite

        // ---- Phase 1: coalesced stream -> u-order smem scatter ----
        // ph = 4g + q; 42 rows x 56 float4 = 2352 float4 over 256 threads.
        {
            const int hoff = 4 * g + q;
            int w4 = tid % 56;
            int r  = tid / 56;
            int hn = r % 14;
            int c  = r / 14;
            #pragma unroll 2
            for (int e4 = tid; e4 < 2352; e4 += THREADS) {
                int w = w4 << 2;
                float4 val = __ldcs((const float4*)(xb +
                    (size_t)c * 50176 + (hn * 16 + hoff) * 224 + w));

                int pw = w & 15;                // 0,4,8,12
                int wn = w >> 4;
                // local u for element 0; elements e at +588e
                int u0 = pw * 588 + c * 196 + hn * 14 + wn;
                Y[u0 +    0] = val.x;
                Y[u0 +  588] = val.y;
                Y[u0 + 1176] = val.z;
                Y[u0 + 1764] = val.w;

                w4 += 32;                       // e4 += 256 carry chain
                int rinc = 4;
                if (w4 >= 56) { w4 -= 56; rinc = 5; }
                hn += rinc;
                if (hn >= 14) { hn -= 14; c++; }
            }
        }
        __syncthreads();

        // ---- Phase 2: contiguous dot over u in [9408q, 9408q+9408) ----
        const int rlo = TILE_F * q, rhi = rlo + TILE_F;
        #pragma unroll
        for (int i = 0; i < 7; i++) {
            int jl = warp + 8 * i;
            if (jl < 49) {
                const int ulo = 768 * jl, uhi = ulo + 768;
                if (ulo >= rhi || uhi <= rlo) continue;   // not in this tile

                if (ulo >= rlo && uhi <= rhi) {
                    // ===== full row: branch-free register-W unroll =====
                    uint32_t ya = ybase + 4u * (ulo - rlo + 4 * lane);
                    unsigned long long p01 = 0, p23 = 0;
                    #pragma unroll
                    for (int k = 0; k < 6; k++) {
                        unsigned long long y01, y23;
                        asm volatile("ld.shared.v2.b64 {%0,%1}, [%2];"
                                     : "=l"(y01), "=l"(y23) : "r"(ya));
                        asm volatile("fma.rn.f32x2 %0, %1, %2, %0;"
                                     : "+l"(p01) : "l"(y01), "l"(wq01[k]));
                        asm volatile("fma.rn.f32x2 %0, %1, %2, %0;"
                                     : "+l"(p23) : "l"(y23), "l"(wq23[k]));
                        ya += 512;              // 128 floats
                    }
                    acc[i] += (__uint_as_float((uint32_t)p01)
                             + __uint_as_float((uint32_t)(p01 >> 32)))
                            + (__uint_as_float((uint32_t)p23)
                             + __uint_as_float((uint32_t)(p23 >> 32)));
                } else {
                    // ===== straddle row (j = 12, 24, 36): smem-W loop =====
                    int clo = max(ulo, rlo);
                    int chi = min(uhi, rhi);
                    int u   = clo + 4 * lane;
                    if (u < chi) {
                        uint32_t ya = ybase + 4u * (u - rlo);
                        uint32_t wa = wbase + 4u * (u - ulo);
                        unsigned long long p01 = 0, p23 = 0;
                        while (u < chi) {
                            unsigned long long y01, y23, w01, w23;
                            asm volatile("ld.shared.v2.b64 {%0,%1}, [%2];"
                                         : "=l"(y01), "=l"(y23) : "r"(ya));
                            asm volatile("ld.shared.v2.b64 {%0,%1}, [%2];"
                                         : "=l"(w01), "=l"(w23) : "r"(wa));
                            asm volatile("fma.rn.f32x2 %0, %1, %2, %0;"
                                         : "+l"(p01) : "l"(y01), "l"(w01));
                            asm volatile("fma.rn.f32x2 %0, %1, %2, %0;"
                                         : "+l"(p23) : "l"(y23), "l"(w23));
                            u  += 128;
                            ya += 512;
                            wa += 512;
                        }
                        acc[i] += (__uint_as_float((uint32_t)p01)
                                 + __uint_as_float((uint32_t)(p01 >> 32)))
                                + (__uint_as_float((uint32_t)p23)
                                 + __uint_as_float((uint32_t)(p23 >> 32)));
                    }
                }
            }
        }
    }

    // ---- final warp reductions + store ----
    const float bv = __ldg(bias);
    #pragma unroll
    for (int i = 0; i < 7; i++) {
        int jl = warp + 8 * i;
        if (jl < 49) {
            float a = acc[i];
            #pragma unroll
            for (int off = 16; off; off >>= 1)
                a += __shfl_xor_sync(0xffffffffu, a, off);
            if (lane == 0)
                out[b * 196 + 49 * g + jl] = a + bv;
        }
    }
}

extern "C" void kernel_launch(void* const* d_in, const int* in_sizes, int n_in,
                              void* d_out, int out_size)
{
    const float* x  = (const float*)d_in[0];
    const float* W  = (const float*)d_in[1];
    const float* bb = (const float*)d_in[2];
    float* out = (float*)d_out;

    const int smem_bytes = (TILE_F + 768) * sizeof(float);  // ~40.7 KB
    cudaFuncSetAttribute(patch_scorer_v12,
                         cudaFuncAttributeMaxDynamicSharedMemorySize, smem_bytes);

    patch_scorer_v12<<<512 * 4, THREADS, smem_bytes>>>(x, W, bb, out);
}